// round 12
// baseline (speedup 1.0000x reference)
#include <cuda_runtime.h>
#include <cfloat>

// Problem shape (fixed by reference): point_cloud [32, 262144, 3] fp32
static constexpr int NB      = 32;
static constexpr int Q_PER_B = 262144 * 3 / 4;        // 196608 float4 per batch
static constexpr int THREADS = 256;
static constexpr int G       = 768;                   // grid; all resident (6/SM * 148 = 888 slots)
static constexpr int ROUNDS  = 4;
static constexpr int BPR     = NB / ROUNDS;           // 8 batches per round
static constexpr int SEG     = 2048;                  // float4 staged per CTA per round (32 KB)
static constexpr int NST     = SEG / THREADS;         // 8 stages
static constexpr int CHB     = Q_PER_B / SEG;         // 96 chunks per batch
static_assert(G * SEG == BPR * Q_PER_B, "round partition must be exact");

// Persistent state — ALL zero-initialized and self-resetting each launch:
//  - g_mn/g_mx: per-(batch,coord) extrema as order-preserving uints with
//    0-sentinel (min stored as max of ~f2ord, max as max of f2ord); reset by
//    the 96th consumer CTA of each batch.
//  - g_arr/g_dep: per-round grid barrier (arrive/depart); 768th departer resets.
__device__ unsigned g_mn[NB * 3];
__device__ unsigned g_mx[NB * 3];
__device__ unsigned g_vdone[NB];
__device__ unsigned g_arr[ROUNDS];
__device__ unsigned g_dep[ROUNDS];

__device__ __forceinline__ unsigned f2ord(float f) {
    unsigned u = __float_as_uint(f);
    return (u & 0x80000000u) ? ~u : (u | 0x80000000u);
}
__device__ __forceinline__ float ord2f(unsigned k) {
    return __uint_as_float((k & 0x80000000u) ? (k ^ 0x80000000u) : ~k);
}

__device__ __forceinline__ void cp_async16(void* smem_dst, const void* gmem_src) {
    unsigned saddr = (unsigned)__cvta_generic_to_shared(smem_dst);
    asm volatile("cp.async.cg.shared.global [%0], [%1], 16;" :: "r"(saddr), "l"(gmem_src));
}
__device__ __forceinline__ void cp_commit()   { asm volatile("cp.async.commit_group;"); }
__device__ __forceinline__ void cp_wait_all() { asm volatile("cp.async.wait_all;" ::: "memory"); }

// Component bookkeeping: float4 at global index q has components
// (q%3,(q+1)%3,(q+2)%3,q%3). Chunk base = (r*G+k)*SEG with SEG=2048 ≡ 2 (mod 3)
// and G ≡ 0 (mod 3)  ->  base%3 = (2k)%3. Stage stride THREADS=256 ≡ 1 (mod 3),
// so with rho = (2k+tid)%3, stage i's float4 has leading component (rho+i)%3 —
// all selection static (stage-indexed) after pre-rotating by rho.

__global__ void __launch_bounds__(THREADS, 6)
fused_round_kernel(const float4* __restrict__ p, float4* __restrict__ out) {
    __shared__ float4 buf[SEG];                 // 32 KB staging (per-thread-private slots)
    __shared__ float  sred[6][THREADS / 32];
    __shared__ float  cst[6];

    const int tid = threadIdx.x;
    const int k   = blockIdx.x;
    const int rho = (2 * k + tid) % 3;

    // Prefetch round 0 while everything else warms up.
    {
        const float4* src = p + (size_t)k * SEG;
        #pragma unroll
        for (int i = 0; i < NST; i++)
            cp_async16(&buf[i * THREADS + tid], &src[i * THREADS + tid]);
        cp_commit();
    }

    for (int r = 0; r < ROUNDS; r++) {
        const size_t base = (size_t)(r * G + k) * SEG;
        const int b = r * BPR + k / CHB;

        cp_wait_all();                          // this thread's staged data ready

        // ── min/max over own staged data (single DRAM read, reused below) ──
        float mnA[3] = {  FLT_MAX,  FLT_MAX,  FLT_MAX };
        float mxA[3] = { -FLT_MAX, -FLT_MAX, -FLT_MAX };
        #pragma unroll
        for (int i = 0; i < NST; i++) {
            const float4 v = buf[i * THREADS + tid];
            const int l0 = i % 3, l1 = (i + 1) % 3, l2 = (i + 2) % 3;
            mnA[l0] = fminf(mnA[l0], fminf(v.x, v.w));
            mxA[l0] = fmaxf(mxA[l0], fmaxf(v.x, v.w));
            mnA[l1] = fminf(mnA[l1], v.y);
            mxA[l1] = fmaxf(mxA[l1], v.y);
            mnA[l2] = fminf(mnA[l2], v.z);
            mxA[l2] = fmaxf(mxA[l2], v.z);
        }
        // Un-rotate: comp c lives in slot (c - rho + 3) % 3
        float mn0, mn1, mn2, mx0, mx1, mx2;
        if (rho == 0)      { mn0=mnA[0]; mn1=mnA[1]; mn2=mnA[2]; mx0=mxA[0]; mx1=mxA[1]; mx2=mxA[2]; }
        else if (rho == 1) { mn0=mnA[2]; mn1=mnA[0]; mn2=mnA[1]; mx0=mxA[2]; mx1=mxA[0]; mx2=mxA[1]; }
        else               { mn0=mnA[1]; mn1=mnA[2]; mn2=mnA[0]; mx0=mxA[1]; mx1=mxA[2]; mx2=mxA[0]; }

        #pragma unroll
        for (int off = 16; off > 0; off >>= 1) {
            mn0 = fminf(mn0, __shfl_xor_sync(0xFFFFFFFFu, mn0, off));
            mn1 = fminf(mn1, __shfl_xor_sync(0xFFFFFFFFu, mn1, off));
            mn2 = fminf(mn2, __shfl_xor_sync(0xFFFFFFFFu, mn2, off));
            mx0 = fmaxf(mx0, __shfl_xor_sync(0xFFFFFFFFu, mx0, off));
            mx1 = fmaxf(mx1, __shfl_xor_sync(0xFFFFFFFFu, mx1, off));
            mx2 = fmaxf(mx2, __shfl_xor_sync(0xFFFFFFFFu, mx2, off));
        }
        {
            const int w = tid >> 5, lane = tid & 31;
            if (lane == 0) {
                sred[0][w] = mn0; sred[1][w] = mn1; sred[2][w] = mn2;
                sred[3][w] = mx0; sred[4][w] = mx1; sred[5][w] = mx2;
            }
        }
        __syncthreads();
        if (tid < 6) {
            float v = sred[tid][0];
            if (tid < 3) {
                #pragma unroll
                for (int j = 1; j < THREADS / 32; j++) v = fminf(v, sred[tid][j]);
                atomicMax(&g_mn[b * 3 + tid], ~f2ord(v));       // RED.MAX, 0-sentinel
            } else {
                #pragma unroll
                for (int j = 1; j < THREADS / 32; j++) v = fmaxf(v, sred[tid][j]);
                atomicMax(&g_mx[b * 3 + (tid - 3)], f2ord(v));
            }
        }

        // ── grid barrier r: all extrema published before anyone reads them ──
        __syncthreads();                        // CTA-order the REDs before the fence
        if (tid == 0) {
            __threadfence();                    // cumulative: REDs device-visible
            atomicAdd(&g_arr[r], 1u);
            while (__ldcg((const unsigned*)&g_arr[r]) < (unsigned)G)
                __nanosleep(64);
            __threadfence();                    // acquire
        }
        __syncthreads();

        // ── finalized constants (must bypass L1: lines cached in prior rounds) ──
        if (tid < 6) {
            cst[tid] = (tid < 3) ? ord2f(~__ldcg(&g_mn[b * 3 + tid]))
                                 : ord2f( __ldcg(&g_mx[b * 3 + (tid - 3)]));
        }
        __syncthreads();

        // Same RN /40 as reference, then reciprocal-multiply per point.
        const float mnc[3]  = { cst[0], cst[1], cst[2] };
        const float invc[3] = { 1.0f / ((cst[3] - cst[0]) / 40.0f),
                                1.0f / ((cst[4] - cst[1]) / 40.0f),
                                1.0f / ((cst[5] - cst[2]) / 40.0f) };
        // Pre-rotate by rho: slot s covers component (rho+s)%3.
        float mnR[3], ivR[3];
        #pragma unroll
        for (int s2 = 0; s2 < 3; s2++) {
            const int c = (rho + s2) < 3 ? (rho + s2) : (rho + s2 - 3);
            mnR[s2] = mnc[c];
            ivR[s2] = invc[c];
        }

        // ── voxelize from SMEM (no second DRAM/L2 read of the input) ──
        #pragma unroll
        for (int i = 0; i < NST; i++) {
            const float4 v = buf[i * THREADS + tid];
            const int u0 = i % 3, u1 = (i + 1) % 3, u2 = (i + 2) % 3;
            float4 res;
            res.x = floorf((v.x - mnR[u0]) * ivR[u0]);
            res.y = floorf((v.y - mnR[u1]) * ivR[u1]);
            res.z = floorf((v.z - mnR[u2]) * ivR[u2]);
            res.w = floorf((v.w - mnR[u0]) * ivR[u0]);
            __stcs(&out[base + i * THREADS + tid], res);
        }

        // ── bookkeeping: barrier depart + per-batch reset for graph replay ──
        if (tid == 0) {
            const unsigned d = atomicAdd(&g_dep[r], 1u);
            if (d == (unsigned)(G - 1)) { g_arr[r] = 0u; g_dep[r] = 0u; }
            const unsigned vd = atomicAdd(&g_vdone[b], 1u);
            if (vd == (unsigned)(CHB - 1)) {
                #pragma unroll
                for (int j = 0; j < 3; j++) { g_mn[b * 3 + j] = 0u; g_mx[b * 3 + j] = 0u; }
                g_vdone[b] = 0u;
            }
        }

        // Prefetch next round. Per-thread slot ownership: thread t only ever
        // writes/reads buf[i*256+t]; all its LDS results above are already
        // consumed (data deps into the STGs), so overwrite is safe.
        if (r + 1 < ROUNDS) {
            const float4* src = p + (size_t)((r + 1) * G + k) * SEG;
            #pragma unroll
            for (int i = 0; i < NST; i++)
                cp_async16(&buf[i * THREADS + tid], &src[i * THREADS + tid]);
            cp_commit();
        }
    }
}

extern "C" void kernel_launch(void* const* d_in, const int* in_sizes, int n_in,
                              void* d_out, int out_size) {
    const float4* p = (const float4*)d_in[0];
    float4* o = (float4*)d_out;
    fused_round_kernel<<<G, THREADS>>>(p, o);
}

// round 13
// speedup vs baseline: 1.1543x; 1.1543x over previous
#include <cuda_runtime.h>
#include <cfloat>

// Problem shape (fixed by reference): point_cloud [32, 262144, 3] fp32
static constexpr int NB       = 32;
static constexpr int NPTS     = 262144;
static constexpr int F_PER_B  = NPTS * 3;        // 786432 floats per batch
static constexpr int Q_PER_B  = F_PER_B / 4;     // 196608 float4 per batch

static constexpr int THREADS  = 256;
static constexpr int BLOCKS1  = 32;              // pass-1 blocks/batch
static constexpr int CHUNK1   = Q_PER_B / BLOCKS1;   // 6144 float4/block
static constexpr int ITER1    = CHUNK1 / (3 * THREADS); // 8
static constexpr int BLOCKS2  = 64;              // pass-2 blocks/batch
static constexpr int CHUNK2   = Q_PER_B / BLOCKS2;   // 3072 float4/block
static constexpr int ITER2    = CHUNK2 / (3 * THREADS); // 4

// Per-(batch, quantity, block) partials; written unconditionally each launch
// -> no init kernel, no atomics, graph-replay safe.
// Quantity: 0..2 = min(x,y,z), 3..5 = max(x,y,z).
__device__ float g_part[NB][6][BLOCKS1];

// Component bookkeeping: float4 at index idx has components
// ((idx)%3,(idx+1)%3,(idx+2)%3,(idx)%3). All chunk bases are multiples of 3
// and the iteration stride THREADS=256 ≡ 1 (mod 3), so with r = tid%3 the
// float4 at unrolled sub-iter u has leading component (r+u)%3; all selection
// static after pre-rotating accumulators/constants by r.

// ───────────────── Pass 1: per-batch per-coord min/max partials ─────────────
__global__ void __launch_bounds__(THREADS)
minmax_kernel(const float4* __restrict__ p) {
    const int b = blockIdx.y;
    const float4* pb = p + (size_t)b * Q_PER_B + blockIdx.x * CHUNK1;
    const int tid = threadIdx.x;
    const int r = tid % 3;

    float mnA0 =  FLT_MAX, mnA1 =  FLT_MAX, mnA2 =  FLT_MAX;
    float mxA0 = -FLT_MAX, mxA1 = -FLT_MAX, mxA2 = -FLT_MAX;

    #pragma unroll 4
    for (int ko = 0; ko < ITER1; ko++) {
        const float4 a = pb[(ko * 3 + 0) * THREADS + tid];  // default policy: fills L2 for pass 2
        const float4 d = pb[(ko * 3 + 1) * THREADS + tid];
        const float4 c = pb[(ko * 3 + 2) * THREADS + tid];
        mnA0 = fminf(mnA0, fminf(a.x, a.w)); mxA0 = fmaxf(mxA0, fmaxf(a.x, a.w));
        mnA1 = fminf(mnA1, a.y);             mxA1 = fmaxf(mxA1, a.y);
        mnA2 = fminf(mnA2, a.z);             mxA2 = fmaxf(mxA2, a.z);
        mnA1 = fminf(mnA1, fminf(d.x, d.w)); mxA1 = fmaxf(mxA1, fmaxf(d.x, d.w));
        mnA2 = fminf(mnA2, d.y);             mxA2 = fmaxf(mxA2, d.y);
        mnA0 = fminf(mnA0, d.z);             mxA0 = fmaxf(mxA0, d.z);
        mnA2 = fminf(mnA2, fminf(c.x, c.w)); mxA2 = fmaxf(mxA2, fmaxf(c.x, c.w));
        mnA0 = fminf(mnA0, c.y);             mxA0 = fmaxf(mxA0, c.y);
        mnA1 = fminf(mnA1, c.z);             mxA1 = fmaxf(mxA1, c.z);
    }

    // Un-rotate: comp k lives in slot (k - r + 3) % 3
    float mn0, mn1, mn2, mx0, mx1, mx2;
    if (r == 0)      { mn0 = mnA0; mn1 = mnA1; mn2 = mnA2; mx0 = mxA0; mx1 = mxA1; mx2 = mxA2; }
    else if (r == 1) { mn0 = mnA2; mn1 = mnA0; mn2 = mnA1; mx0 = mxA2; mx1 = mxA0; mx2 = mxA1; }
    else             { mn0 = mnA1; mn1 = mnA2; mn2 = mnA0; mx0 = mxA1; mx1 = mxA2; mx2 = mxA0; }

    #pragma unroll
    for (int off = 16; off > 0; off >>= 1) {
        mn0 = fminf(mn0, __shfl_xor_sync(0xFFFFFFFFu, mn0, off));
        mn1 = fminf(mn1, __shfl_xor_sync(0xFFFFFFFFu, mn1, off));
        mn2 = fminf(mn2, __shfl_xor_sync(0xFFFFFFFFu, mn2, off));
        mx0 = fmaxf(mx0, __shfl_xor_sync(0xFFFFFFFFu, mx0, off));
        mx1 = fmaxf(mx1, __shfl_xor_sync(0xFFFFFFFFu, mx1, off));
        mx2 = fmaxf(mx2, __shfl_xor_sync(0xFFFFFFFFu, mx2, off));
    }

    __shared__ float s[6][THREADS / 32];
    const int w = tid >> 5, lane = tid & 31;
    if (lane == 0) {
        s[0][w] = mn0; s[1][w] = mn1; s[2][w] = mn2;
        s[3][w] = mx0; s[4][w] = mx1; s[5][w] = mx2;
    }
    __syncthreads();

    if (tid < 6) {
        float v = s[tid][0];
        if (tid < 3) {
            #pragma unroll
            for (int k = 1; k < THREADS / 32; k++) v = fminf(v, s[tid][k]);
        } else {
            #pragma unroll
            for (int k = 1; k < THREADS / 32; k++) v = fmaxf(v, s[tid][k]);
        }
        g_part[b][tid][blockIdx.x] = v;
    }
}

// ───────────────── Pass 2: voxels = floor((p - min) / bin_width) ────────────
// REVERSED block->data mapping: earliest-dispatched voxel blocks process the
// END of the tensor and we sweep backwards. All input is L2-resident when the
// first blocks run; as output write-allocations advance an eviction front,
// each block reads the freshest surviving region -> higher L2 read hit rate
// than the forward sweep (which raced its own evictions).
__global__ void __launch_bounds__(THREADS, 4)
voxel_kernel(const float4* __restrict__ p, float4* __restrict__ out) {
    const int b = (NB - 1) - blockIdx.y;            // reverse batch order
    const int cchunk = (BLOCKS2 - 1) - blockIdx.x;  // reverse chunk order
    const int tid = threadIdx.x;

    // Prologue: warps 0..5 each reduce the 32 per-block partials for one quantity.
    __shared__ float cst[6];
    {
        const int w = tid >> 5, lane = tid & 31;
        if (w < 6) {
            float v = g_part[b][w][lane];
            if (w < 3) {
                #pragma unroll
                for (int off = 16; off > 0; off >>= 1)
                    v = fminf(v, __shfl_xor_sync(0xFFFFFFFFu, v, off));
            } else {
                #pragma unroll
                for (int off = 16; off > 0; off >>= 1)
                    v = fmaxf(v, __shfl_xor_sync(0xFFFFFFFFu, v, off));
            }
            if (lane == 0) cst[w] = v;
        }
    }
    __syncthreads();

    // Same RN /40 as reference, then reciprocal-multiply per point
    // (rel err << 1e-3 threshold).
    const float mnc[3]  = { cst[0], cst[1], cst[2] };
    const float invc[3] = { 1.0f / ((cst[3] - cst[0]) / 40.0f),
                            1.0f / ((cst[4] - cst[1]) / 40.0f),
                            1.0f / ((cst[5] - cst[2]) / 40.0f) };

    // Pre-rotate by r = tid % 3: slot s covers component (r+s)%3.
    const int r = tid % 3;
    const float mn_0 = mnc[r], mn_1 = mnc[(r + 1) % 3], mn_2 = mnc[(r + 2) % 3];
    const float iv_0 = invc[r], iv_1 = invc[(r + 1) % 3], iv_2 = invc[(r + 2) % 3];

    const size_t base = (size_t)b * Q_PER_B + (size_t)cchunk * CHUNK2;
    const float4* pb = p + base;
    float4* ob = out + base;

    // Double-buffered main loop (~6 LDG.128 in flight/thread).
    float4 a = __ldcs(&pb[0 * THREADS + tid]);
    float4 d = __ldcs(&pb[1 * THREADS + tid]);
    float4 c = __ldcs(&pb[2 * THREADS + tid]);

    #pragma unroll
    for (int ko = 0; ko < ITER2; ko++) {
        float4 an, dn, cn;
        if (ko + 1 < ITER2) {
            an = __ldcs(&pb[((ko + 1) * 3 + 0) * THREADS + tid]);
            dn = __ldcs(&pb[((ko + 1) * 3 + 1) * THREADS + tid]);
            cn = __ldcs(&pb[((ko + 1) * 3 + 2) * THREADS + tid]);
        }

        float4 ra, rd, rc;
        // u=0: comps (0,1,2,0) after rotation
        ra.x = floorf((a.x - mn_0) * iv_0);
        ra.y = floorf((a.y - mn_1) * iv_1);
        ra.z = floorf((a.z - mn_2) * iv_2);
        ra.w = floorf((a.w - mn_0) * iv_0);
        // u=1: comps (1,2,0,1)
        rd.x = floorf((d.x - mn_1) * iv_1);
        rd.y = floorf((d.y - mn_2) * iv_2);
        rd.z = floorf((d.z - mn_0) * iv_0);
        rd.w = floorf((d.w - mn_1) * iv_1);
        // u=2: comps (2,0,1,2)
        rc.x = floorf((c.x - mn_2) * iv_2);
        rc.y = floorf((c.y - mn_0) * iv_0);
        rc.z = floorf((c.z - mn_1) * iv_1);
        rc.w = floorf((c.w - mn_2) * iv_2);

        __stcs(&ob[(ko * 3 + 0) * THREADS + tid], ra);
        __stcs(&ob[(ko * 3 + 1) * THREADS + tid], rd);
        __stcs(&ob[(ko * 3 + 2) * THREADS + tid], rc);

        a = an; d = dn; c = cn;
    }
}

extern "C" void kernel_launch(void* const* d_in, const int* in_sizes, int n_in,
                              void* d_out, int out_size) {
    const float4* p = (const float4*)d_in[0];
    float4* o = (float4*)d_out;

    minmax_kernel<<<dim3(BLOCKS1, NB), THREADS>>>(p);
    voxel_kernel<<<dim3(BLOCKS2, NB), THREADS>>>(p, o);
}

// round 14
// speedup vs baseline: 1.1770x; 1.0197x over previous
#include <cuda_runtime.h>
#include <cfloat>

// Problem shape (fixed by reference): point_cloud [32, 262144, 3] fp32
static constexpr int NB       = 32;
static constexpr int NPTS     = 262144;
static constexpr int F_PER_B  = NPTS * 3;        // 786432 floats per batch
static constexpr int Q_PER_B  = F_PER_B / 4;     // 196608 float4 per batch

static constexpr int THREADS  = 256;
static constexpr int BLOCKS1  = 32;              // pass-1 blocks/batch
static constexpr int CHUNK1   = Q_PER_B / BLOCKS1;   // 6144 float4/block
static constexpr int ITER1    = CHUNK1 / (3 * THREADS); // 8
static constexpr int BLOCKS2  = 64;              // pass-2 blocks/batch
static constexpr int CHUNK2   = Q_PER_B / BLOCKS2;   // 3072 float4/block
static constexpr int ITER2    = CHUNK2 / (3 * THREADS); // 4

// Per-(batch, quantity, block) partials; written unconditionally each launch
// -> no init kernel, no atomics, graph-replay safe.
// Quantity: 0..2 = min(x,y,z), 3..5 = max(x,y,z).
__device__ float g_part[NB][6][BLOCKS1];

// Component bookkeeping: float4 at index idx has components
// ((idx)%3,(idx+1)%3,(idx+2)%3,(idx)%3). All chunk bases are multiples of 3
// and the iteration stride THREADS=256 ≡ 1 (mod 3), so with r = tid%3 the
// float4 at unrolled sub-iter u has leading component (r+u)%3; all selection
// static after pre-rotating accumulators/constants by r.

// ───────────────── Pass 1: per-batch per-coord min/max partials ─────────────
__global__ void __launch_bounds__(THREADS)
minmax_kernel(const float4* __restrict__ p) {
    const int b = blockIdx.y;
    const float4* pb = p + (size_t)b * Q_PER_B + blockIdx.x * CHUNK1;
    const int tid = threadIdx.x;
    const int r = tid % 3;

    float mnA0 =  FLT_MAX, mnA1 =  FLT_MAX, mnA2 =  FLT_MAX;
    float mxA0 = -FLT_MAX, mxA1 = -FLT_MAX, mxA2 = -FLT_MAX;

    #pragma unroll 4
    for (int ko = 0; ko < ITER1; ko++) {
        const float4 a = pb[(ko * 3 + 0) * THREADS + tid];  // default policy: fills L2 for pass 2
        const float4 d = pb[(ko * 3 + 1) * THREADS + tid];
        const float4 c = pb[(ko * 3 + 2) * THREADS + tid];
        mnA0 = fminf(mnA0, fminf(a.x, a.w)); mxA0 = fmaxf(mxA0, fmaxf(a.x, a.w));
        mnA1 = fminf(mnA1, a.y);             mxA1 = fmaxf(mxA1, a.y);
        mnA2 = fminf(mnA2, a.z);             mxA2 = fmaxf(mxA2, a.z);
        mnA1 = fminf(mnA1, fminf(d.x, d.w)); mxA1 = fmaxf(mxA1, fmaxf(d.x, d.w));
        mnA2 = fminf(mnA2, d.y);             mxA2 = fmaxf(mxA2, d.y);
        mnA0 = fminf(mnA0, d.z);             mxA0 = fmaxf(mxA0, d.z);
        mnA2 = fminf(mnA2, fminf(c.x, c.w)); mxA2 = fmaxf(mxA2, fmaxf(c.x, c.w));
        mnA0 = fminf(mnA0, c.y);             mxA0 = fmaxf(mxA0, c.y);
        mnA1 = fminf(mnA1, c.z);             mxA1 = fmaxf(mxA1, c.z);
    }

    // Un-rotate: comp k lives in slot (k - r + 3) % 3
    float mn0, mn1, mn2, mx0, mx1, mx2;
    if (r == 0)      { mn0 = mnA0; mn1 = mnA1; mn2 = mnA2; mx0 = mxA0; mx1 = mxA1; mx2 = mxA2; }
    else if (r == 1) { mn0 = mnA2; mn1 = mnA0; mn2 = mnA1; mx0 = mxA2; mx1 = mxA0; mx2 = mxA1; }
    else             { mn0 = mnA1; mn1 = mnA2; mn2 = mnA0; mx0 = mxA1; mx1 = mxA2; mx2 = mxA0; }

    #pragma unroll
    for (int off = 16; off > 0; off >>= 1) {
        mn0 = fminf(mn0, __shfl_xor_sync(0xFFFFFFFFu, mn0, off));
        mn1 = fminf(mn1, __shfl_xor_sync(0xFFFFFFFFu, mn1, off));
        mn2 = fminf(mn2, __shfl_xor_sync(0xFFFFFFFFu, mn2, off));
        mx0 = fmaxf(mx0, __shfl_xor_sync(0xFFFFFFFFu, mx0, off));
        mx1 = fmaxf(mx1, __shfl_xor_sync(0xFFFFFFFFu, mx1, off));
        mx2 = fmaxf(mx2, __shfl_xor_sync(0xFFFFFFFFu, mx2, off));
    }

    __shared__ float s[6][THREADS / 32];
    const int w = tid >> 5, lane = tid & 31;
    if (lane == 0) {
        s[0][w] = mn0; s[1][w] = mn1; s[2][w] = mn2;
        s[3][w] = mx0; s[4][w] = mx1; s[5][w] = mx2;
    }
    __syncthreads();

    if (tid < 6) {
        float v = s[tid][0];
        if (tid < 3) {
            #pragma unroll
            for (int k = 1; k < THREADS / 32; k++) v = fminf(v, s[tid][k]);
        } else {
            #pragma unroll
            for (int k = 1; k < THREADS / 32; k++) v = fmaxf(v, s[tid][k]);
        }
        g_part[b][tid][blockIdx.x] = v;
    }
    __syncthreads();

    // PDL: this block's global writes are done -> allow the dependent
    // voxel grid to start launching.
    cudaTriggerProgrammaticLaunchCompletion();
}

// ───────────────── Pass 2: voxels = floor((p - min) / bin_width) ────────────
// PDL secondary: front-issue the first three input loads (independent of
// pass 1), then cudaGridDependencySynchronize() before touching g_part.
__global__ void __launch_bounds__(THREADS, 4)
voxel_kernel(const float4* __restrict__ p, float4* __restrict__ out) {
    const int b = blockIdx.y;
    const int tid = threadIdx.x;

    const size_t base = (size_t)b * Q_PER_B + blockIdx.x * CHUNK2;
    const float4* pb = p + base;
    float4* ob = out + base;

    // Early loads: overlap with the primary grid's drain.
    float4 a = __ldcs(&pb[0 * THREADS + tid]);
    float4 d = __ldcs(&pb[1 * THREADS + tid]);
    float4 c = __ldcs(&pb[2 * THREADS + tid]);

    // Wait for the minmax grid to fully complete (its g_part writes visible).
    cudaGridDependencySynchronize();

    // Prologue: warps 0..5 each reduce the 32 per-block partials for one quantity.
    __shared__ float cst[6];
    {
        const int w = tid >> 5, lane = tid & 31;
        if (w < 6) {
            float v = g_part[b][w][lane];
            if (w < 3) {
                #pragma unroll
                for (int off = 16; off > 0; off >>= 1)
                    v = fminf(v, __shfl_xor_sync(0xFFFFFFFFu, v, off));
            } else {
                #pragma unroll
                for (int off = 16; off > 0; off >>= 1)
                    v = fmaxf(v, __shfl_xor_sync(0xFFFFFFFFu, v, off));
            }
            if (lane == 0) cst[w] = v;
        }
    }
    __syncthreads();

    // Same RN /40 as reference, then reciprocal-multiply per point
    // (rel err << 1e-3 threshold).
    const float mnc[3]  = { cst[0], cst[1], cst[2] };
    const float invc[3] = { 1.0f / ((cst[3] - cst[0]) / 40.0f),
                            1.0f / ((cst[4] - cst[1]) / 40.0f),
                            1.0f / ((cst[5] - cst[2]) / 40.0f) };

    // Pre-rotate by r = tid % 3: slot s covers component (r+s)%3.
    const int r = tid % 3;
    const float mn_0 = mnc[r], mn_1 = mnc[(r + 1) % 3], mn_2 = mnc[(r + 2) % 3];
    const float iv_0 = invc[r], iv_1 = invc[(r + 1) % 3], iv_2 = invc[(r + 2) % 3];

    #pragma unroll
    for (int ko = 0; ko < ITER2; ko++) {
        float4 an, dn, cn;
        if (ko + 1 < ITER2) {
            an = __ldcs(&pb[((ko + 1) * 3 + 0) * THREADS + tid]);
            dn = __ldcs(&pb[((ko + 1) * 3 + 1) * THREADS + tid]);
            cn = __ldcs(&pb[((ko + 1) * 3 + 2) * THREADS + tid]);
        }

        float4 ra, rd, rc;
        // u=0: comps (0,1,2,0) after rotation
        ra.x = floorf((a.x - mn_0) * iv_0);
        ra.y = floorf((a.y - mn_1) * iv_1);
        ra.z = floorf((a.z - mn_2) * iv_2);
        ra.w = floorf((a.w - mn_0) * iv_0);
        // u=1: comps (1,2,0,1)
        rd.x = floorf((d.x - mn_1) * iv_1);
        rd.y = floorf((d.y - mn_2) * iv_2);
        rd.z = floorf((d.z - mn_0) * iv_0);
        rd.w = floorf((d.w - mn_1) * iv_1);
        // u=2: comps (2,0,1,2)
        rc.x = floorf((c.x - mn_2) * iv_2);
        rc.y = floorf((c.y - mn_0) * iv_0);
        rc.z = floorf((c.z - mn_1) * iv_1);
        rc.w = floorf((c.w - mn_2) * iv_2);

        __stcs(&ob[(ko * 3 + 0) * THREADS + tid], ra);
        __stcs(&ob[(ko * 3 + 1) * THREADS + tid], rd);
        __stcs(&ob[(ko * 3 + 2) * THREADS + tid], rc);

        a = an; d = dn; c = cn;
    }
}

extern "C" void kernel_launch(void* const* d_in, const int* in_sizes, int n_in,
                              void* d_out, int out_size) {
    const float4* p = (const float4*)d_in[0];
    float4* o = (float4*)d_out;

    minmax_kernel<<<dim3(BLOCKS1, NB), THREADS>>>(p);

    // Voxel kernel launched with programmatic stream serialization: it may
    // begin launching while minmax drains; correctness is enforced by
    // cudaGridDependencySynchronize() inside the kernel.
    cudaLaunchConfig_t cfg = {};
    cfg.gridDim  = dim3(BLOCKS2, NB);
    cfg.blockDim = dim3(THREADS);
    cfg.dynamicSmemBytes = 0;
    cfg.stream = 0;
    cudaLaunchAttribute attr[1];
    attr[0].id = cudaLaunchAttributeProgrammaticStreamSerialization;
    attr[0].val.programmaticStreamSerializationAllowed = 1;
    cfg.attrs = attr;
    cfg.numAttrs = 1;
    cudaLaunchKernelEx(&cfg, voxel_kernel, p, o);
}